// round 6
// baseline (speedup 1.0000x reference)
#include <cuda_runtime.h>
#include <cstdint>

#define N_MAX 100000
#define E_MAX 3200000

// Scratch: __device__ globals (no allocation allowed)
__device__ float g_deg[N_MAX];
__device__ float g_dinv[N_MAX];
__device__ int   g_count[N_MAX];
__device__ int   g_offsets[N_MAX + 1];
__device__ int   g_cursor[N_MAX];
__device__ unsigned long long g_perm[E_MAX];   // packed (row:int32 | coef:f32)
__device__ int   g_is64;                       // 1 if edge_index is int64, else int32

__device__ __forceinline__ int get_idx(const void* ei, int is64, long pos) {
    if (is64) return (int)((const long long*)ei)[pos];
    return ((const int*)ei)[pos];
}

// ---------------------------------------------------------------------------
// 1) setup: deg = 1.0, count = 0; thread 0 also detects the index dtype.
//    int64 indices < 2^31 (little-endian) have all-zero odd 32-bit words.
__global__ void k_setup(const unsigned int* __restrict__ eiw, int n) {
    int i = blockIdx.x * blockDim.x + threadIdx.x;
    if (i < n) { g_deg[i] = 1.0f; g_count[i] = 0; }
    if (i == 0) {
        int all0 = 1;
        #pragma unroll
        for (int k = 0; k < 64; k++) all0 &= (eiw[2 * k + 1] == 0u);
        g_is64 = all0;
    }
}

// 2) per edge: deg[col] += ew ; count[col] += 1
__global__ void k_count_deg(const void* __restrict__ ei,
                            const float* __restrict__ ew, int E) {
    int e = blockIdx.x * blockDim.x + threadIdx.x;
    if (e < E) {
        int is64 = g_is64;
        int c = get_idx(ei, is64, (long)E + e);
        atomicAdd(&g_deg[c], __ldcs(&ew[e]));
        atomicAdd(&g_count[c], 1);
    }
}

// 3) single-block scan (+ fused dinv): offsets = exclusive_scan(count); cursor = offsets
__global__ void k_scan(int n, int E) {
    __shared__ int s[1024];
    int t = threadIdx.x;
    int chunk = (n + 1023) / 1024;
    int lo = t * chunk;
    int hi = lo + chunk; if (hi > n) hi = n;

    int sum = 0;
    for (int i = lo; i < hi; i++) {
        sum += g_count[i];
        float d = g_deg[i];
        g_dinv[i] = (d > 0.0f) ? rsqrtf(d) : 0.0f;   // fused dinv
    }
    s[t] = sum;
    __syncthreads();
    for (int d = 1; d < 1024; d <<= 1) {
        int v = (t >= d) ? s[t - d] : 0;
        __syncthreads();
        s[t] += v;
        __syncthreads();
    }
    int run = (t == 0) ? 0 : s[t - 1];
    for (int i = lo; i < hi; i++) {
        g_offsets[i] = run;
        g_cursor[i]  = run;
        run += g_count[i];
    }
    if (t == 0) g_offsets[n] = E;
}

// 4) fill CSR: per edge, compute coef and scatter packed record under col bucket
__global__ void k_fill(const void* __restrict__ ei,
                       const float* __restrict__ ew, int E) {
    int e = blockIdx.x * blockDim.x + threadIdx.x;
    if (e < E) {
        int is64 = g_is64;
        int r = get_idx(ei, is64, e);
        int c = get_idx(ei, is64, (long)E + e);
        float coef = g_dinv[r] * __ldcs(&ew[e]) * g_dinv[c];
        int pos = atomicAdd(&g_cursor[c], 1);
        unsigned long long rec =
            (unsigned long long)(unsigned int)r |
            ((unsigned long long)__float_as_uint(coef) << 32);
        __stcs(&g_perm[pos], rec);   // streaming: read exactly once later
    }
}

// 5) gather: one warp per node, lane l owns float4 chunk l. ILP-2 mainloop.
//    out[c] = dinv[c]^2 * x[c] + sum_{e in CSR[c]} coef_e * x[row_e]
__global__ void k_gather(const float4* __restrict__ x,
                         float4* __restrict__ out, int n) {
    int w    = (blockIdx.x * blockDim.x + threadIdx.x) >> 5;
    int lane = threadIdx.x & 31;
    if (w >= n) return;

    float di = g_dinv[w];
    float s  = di * di;
    float4 v = __ldg(&x[(long)w * 32 + lane]);
    float4 acc0, acc1;
    acc0.x = v.x * s; acc0.y = v.y * s; acc0.z = v.z * s; acc0.w = v.w * s;
    acc1.x = 0.f; acc1.y = 0.f; acc1.z = 0.f; acc1.w = 0.f;

    int beg = g_offsets[w];
    int end = g_offsets[w + 1];
    int j = beg;

    // ILP-2: two independent rec->x->FFMA chains per iteration
    for (; j + 1 < end; j += 2) {
        unsigned long long rec0 = __ldcs(&g_perm[j]);
        unsigned long long rec1 = __ldcs(&g_perm[j + 1]);
        int   r0 = (int)(unsigned int)(rec0 & 0xFFFFFFFFull);
        int   r1 = (int)(unsigned int)(rec1 & 0xFFFFFFFFull);
        float w0 = __uint_as_float((unsigned int)(rec0 >> 32));
        float w1 = __uint_as_float((unsigned int)(rec1 >> 32));
        float4 a = __ldg(&x[(long)r0 * 32 + lane]);
        float4 b = __ldg(&x[(long)r1 * 32 + lane]);
        acc0.x += w0 * a.x; acc0.y += w0 * a.y; acc0.z += w0 * a.z; acc0.w += w0 * a.w;
        acc1.x += w1 * b.x; acc1.y += w1 * b.y; acc1.z += w1 * b.z; acc1.w += w1 * b.w;
    }
    if (j < end) {
        unsigned long long rec = __ldcs(&g_perm[j]);
        int   r  = (int)(unsigned int)(rec & 0xFFFFFFFFull);
        float cw = __uint_as_float((unsigned int)(rec >> 32));
        float4 a = __ldg(&x[(long)r * 32 + lane]);
        acc0.x += cw * a.x; acc0.y += cw * a.y; acc0.z += cw * a.z; acc0.w += cw * a.w;
    }

    float4 o;
    o.x = acc0.x + acc1.x; o.y = acc0.y + acc1.y;
    o.z = acc0.z + acc1.z; o.w = acc0.w + acc1.w;
    __stcs(&out[(long)w * 32 + lane], o);   // write-once: don't pollute L2
}

// ---------------------------------------------------------------------------
extern "C" void kernel_launch(void* const* d_in, const int* in_sizes, int n_in,
                              void* d_out, int out_size) {
    // Bind inputs BY ELEMENT COUNT (robust to metadata ordering):
    //   x: N*128 f32 ; edge_weight: E f32 ; edge_index: 2E (i64 or i32, device-detected)
    int n = out_size / 128;

    const float* x = nullptr;
    int xi = -1;
    for (int i = 0; i < n_in; i++) {
        if (in_sizes[i] == n * 128) { x = (const float*)d_in[i]; xi = i; break; }
    }
    int ia = -1, ib = -1;
    for (int i = 0; i < n_in; i++) {
        if (i == xi) continue;
        if (ia < 0) ia = i; else ib = i;
    }
    const void* ei;
    const float* ew;
    int E;
    if (in_sizes[ia] > in_sizes[ib]) {
        ei = d_in[ia]; ew = (const float*)d_in[ib]; E = in_sizes[ib];
    } else {
        ei = d_in[ib]; ew = (const float*)d_in[ia]; E = in_sizes[ia];
    }

    float* out = (float*)d_out;

    k_setup    <<<(n + 255) / 256, 256>>>((const unsigned int*)ei, n);
    k_count_deg<<<(E + 255) / 256, 256>>>(ei, ew, E);
    k_scan     <<<1, 1024>>>(n, E);
    k_fill     <<<(E + 255) / 256, 256>>>(ei, ew, E);

    long long gt = (long long)n * 32;
    k_gather   <<<(int)((gt + 255) / 256), 256>>>((const float4*)x, (float4*)out, n);
}

// round 7
// speedup vs baseline: 1.2018x; 1.2018x over previous
#include <cuda_runtime.h>
#include <cstdint>

#define N_MAX 100000
#define E_MAX 3200000

// Fixed-point packing for fused (count | deg-sum) atomic:
//   bits [0:42)  : sum of ew in 20-bit fixed point (ew in [0,1))
//   bits [42:64) : edge count
#define FP_SHIFT 20
#define FP_SCALE 1048576.0f          // 2^20
#define FP_INV   (1.0f / 1048576.0f)
#define CNT_SHIFT 42
#define SUM_MASK ((1ull << CNT_SHIFT) - 1ull)

// Scratch: __device__ globals (no allocation allowed)
__device__ unsigned long long g_pack[N_MAX];   // packed count|degsum
__device__ float g_dinv[N_MAX];
__device__ int   g_offsets[N_MAX + 1];
__device__ int   g_cursor[N_MAX];
__device__ unsigned long long g_perm[E_MAX];   // packed (row:int32 | coef:f32)
__device__ int   g_is64;                       // 1 if edge_index is int64, else int32

__device__ __forceinline__ int get_idx(const void* ei, int is64, long pos) {
    if (is64) return (int)((const long long*)ei)[pos];
    return ((const int*)ei)[pos];
}

// ---------------------------------------------------------------------------
// 1) setup: pack = 0; thread 0 detects index dtype (int64 has zero odd words).
__global__ void k_setup(const unsigned int* __restrict__ eiw, int n) {
    int i = blockIdx.x * blockDim.x + threadIdx.x;
    if (i < n) g_pack[i] = 0ull;
    if (i == 0) {
        int all0 = 1;
        #pragma unroll
        for (int k = 0; k < 64; k++) all0 &= (eiw[2 * k + 1] == 0u);
        g_is64 = all0;
    }
}

// 2) per edge: ONE packed atomic accumulates both count and deg-sum at col.
__global__ void k_count_deg(const void* __restrict__ ei,
                            const float* __restrict__ ew, int E) {
    int e = blockIdx.x * blockDim.x + threadIdx.x;
    if (e < E) {
        int is64 = g_is64;
        int c = get_idx(ei, is64, (long)E + e);
        unsigned long long inc =
            (1ull << CNT_SHIFT) |
            (unsigned long long)(ew[e] * FP_SCALE + 0.5f);
        atomicAdd(&g_pack[c], inc);
    }
}

// 3) dinv = rsqrt(1 + degsum)   (self-loop weight 1.0; deg >= 1 always)
__global__ void k_dinv(int n) {
    int i = blockIdx.x * blockDim.x + threadIdx.x;
    if (i < n) {
        unsigned long long p = g_pack[i];
        float deg = 1.0f + (float)(p & SUM_MASK) * FP_INV;
        g_dinv[i] = rsqrtf(deg);
    }
}

// 4) single-block exclusive scan of counts (decoded from pack)
__global__ void k_scan(int n, int E) {
    __shared__ int s[1024];
    int t = threadIdx.x;
    int chunk = (n + 1023) / 1024;
    int lo = t * chunk;
    int hi = lo + chunk; if (hi > n) hi = n;

    int sum = 0;
    for (int i = lo; i < hi; i++) sum += (int)(g_pack[i] >> CNT_SHIFT);
    s[t] = sum;
    __syncthreads();
    for (int d = 1; d < 1024; d <<= 1) {
        int v = (t >= d) ? s[t - d] : 0;
        __syncthreads();
        s[t] += v;
        __syncthreads();
    }
    int run = (t == 0) ? 0 : s[t - 1];
    for (int i = lo; i < hi; i++) {
        g_offsets[i] = run;
        g_cursor[i]  = run;
        run += (int)(g_pack[i] >> CNT_SHIFT);
    }
    if (t == 0) g_offsets[n] = E;
}

// 5) fill CSR: per edge, compute coef and scatter packed record under col bucket
__global__ void k_fill(const void* __restrict__ ei,
                       const float* __restrict__ ew, int E) {
    int e = blockIdx.x * blockDim.x + threadIdx.x;
    if (e < E) {
        int is64 = g_is64;
        int r = get_idx(ei, is64, e);
        int c = get_idx(ei, is64, (long)E + e);
        float coef = g_dinv[r] * ew[e] * g_dinv[c];
        int pos = atomicAdd(&g_cursor[c], 1);
        unsigned long long rec =
            (unsigned long long)(unsigned int)r |
            ((unsigned long long)__float_as_uint(coef) << 32);
        g_perm[pos] = rec;
    }
}

// 6) gather: one warp per node, lane l owns float4 chunk l (exact R4 loop).
//    out[c] = dinv[c]^2 * x[c] + sum_{e in CSR[c]} coef_e * x[row_e]
__global__ void k_gather(const float4* __restrict__ x,
                         float4* __restrict__ out, int n) {
    int w    = (blockIdx.x * blockDim.x + threadIdx.x) >> 5;
    int lane = threadIdx.x & 31;
    if (w >= n) return;

    float di = g_dinv[w];
    float s  = di * di;
    float4 v = __ldg(&x[(long)w * 32 + lane]);
    float4 acc;
    acc.x = v.x * s; acc.y = v.y * s; acc.z = v.z * s; acc.w = v.w * s;

    int beg = g_offsets[w];
    int end = g_offsets[w + 1];

    if (beg < end) {
        unsigned long long rec = g_perm[beg];   // software pipeline: prefetch rec
        for (int j = beg; j < end; j++) {
            unsigned long long next = (j + 1 < end) ? g_perm[j + 1] : 0ull;
            int   r  = (int)(unsigned int)(rec & 0xFFFFFFFFull);
            float cw = __uint_as_float((unsigned int)(rec >> 32));
            float4 xv = __ldg(&x[(long)r * 32 + lane]);
            acc.x += cw * xv.x;
            acc.y += cw * xv.y;
            acc.z += cw * xv.z;
            acc.w += cw * xv.w;
            rec = next;
        }
    }
    out[(long)w * 32 + lane] = acc;
}

// ---------------------------------------------------------------------------
extern "C" void kernel_launch(void* const* d_in, const int* in_sizes, int n_in,
                              void* d_out, int out_size) {
    // Bind inputs BY ELEMENT COUNT (robust to metadata ordering):
    //   x: N*128 f32 ; edge_weight: E f32 ; edge_index: 2E (i64 or i32, device-detected)
    int n = out_size / 128;

    const float* x = nullptr;
    int xi = -1;
    for (int i = 0; i < n_in; i++) {
        if (in_sizes[i] == n * 128) { x = (const float*)d_in[i]; xi = i; break; }
    }
    int ia = -1, ib = -1;
    for (int i = 0; i < n_in; i++) {
        if (i == xi) continue;
        if (ia < 0) ia = i; else ib = i;
    }
    const void* ei;
    const float* ew;
    int E;
    if (in_sizes[ia] > in_sizes[ib]) {
        ei = d_in[ia]; ew = (const float*)d_in[ib]; E = in_sizes[ib];
    } else {
        ei = d_in[ib]; ew = (const float*)d_in[ia]; E = in_sizes[ia];
    }

    float* out = (float*)d_out;

    k_setup    <<<(n + 255) / 256, 256>>>((const unsigned int*)ei, n);
    k_count_deg<<<(E + 255) / 256, 256>>>(ei, ew, E);
    k_dinv     <<<(n + 255) / 256, 256>>>(n);
    k_scan     <<<1, 1024>>>(n, E);
    k_fill     <<<(E + 255) / 256, 256>>>(ei, ew, E);

    long long gt = (long long)n * 32;
    k_gather   <<<(int)((gt + 255) / 256), 256>>>((const float4*)x, (float4*)out, n);
}

// round 8
// speedup vs baseline: 2.2371x; 1.8615x over previous
#include <cuda_runtime.h>
#include <cstdint>

#define N_MAX 100000
#define E_MAX 3200000

// Fixed-point packing for fused (count | deg-sum) atomic:
//   bits [0:42)  : sum of ew in 20-bit fixed point (ew in [0,1))
//   bits [42:64) : edge count
#define FP_SCALE 1048576.0f          // 2^20
#define FP_INV   (1.0f / 1048576.0f)
#define CNT_SHIFT 42
#define SUM_MASK ((1ull << CNT_SHIFT) - 1ull)

#define SCAN_BLK 1024                 // elements (and threads) per scan block
#define MAX_SCAN_BLOCKS 128           // ceil(N_MAX/SCAN_BLK) = 98

// Scratch: __device__ globals (no allocation allowed)
__device__ unsigned long long g_pack[N_MAX];   // packed count|degsum
__device__ float g_dinv[N_MAX];
__device__ int   g_offsets[N_MAX + 1];
__device__ int   g_cursor[N_MAX];
__device__ int   g_bsum[MAX_SCAN_BLOCKS];      // per-block partial sums
__device__ int   g_btop[MAX_SCAN_BLOCKS];      // exclusive scan of g_bsum
__device__ unsigned long long g_perm[E_MAX];   // packed (row:int32 | coef:f32)
__device__ int   g_is64;                       // 1 if edge_index is int64, else int32

__device__ __forceinline__ int get_idx(const void* ei, int is64, long pos) {
    if (is64) return (int)((const long long*)ei)[pos];
    return ((const int*)ei)[pos];
}

// ---------------------------------------------------------------------------
// 1) setup: pack = 0; thread 0 detects index dtype (int64 has zero odd words).
__global__ void k_setup(const unsigned int* __restrict__ eiw, int n) {
    int i = blockIdx.x * blockDim.x + threadIdx.x;
    if (i < n) g_pack[i] = 0ull;
    if (i == 0) {
        int all0 = 1;
        #pragma unroll
        for (int k = 0; k < 64; k++) all0 &= (eiw[2 * k + 1] == 0u);
        g_is64 = all0;
    }
}

// 2) per edge: ONE packed atomic accumulates both count and deg-sum at col.
__global__ void k_count_deg(const void* __restrict__ ei,
                            const float* __restrict__ ew, int E) {
    int e = blockIdx.x * blockDim.x + threadIdx.x;
    if (e < E) {
        int is64 = g_is64;
        int c = get_idx(ei, is64, (long)E + e);
        unsigned long long inc =
            (1ull << CNT_SHIFT) |
            (unsigned long long)(ew[e] * FP_SCALE + 0.5f);
        atomicAdd(&g_pack[c], inc);
    }
}

// 3a) per-block partial sums of counts (coalesced) + fused dinv computation.
__global__ void k_scan_partial(int n) {
    __shared__ int s[SCAN_BLK];
    int t = threadIdx.x;
    int i = blockIdx.x * SCAN_BLK + t;
    int cnt = 0;
    if (i < n) {
        unsigned long long p = g_pack[i];
        cnt = (int)(p >> CNT_SHIFT);
        float deg = 1.0f + (float)(p & SUM_MASK) * FP_INV;
        g_dinv[i] = rsqrtf(deg);
    }
    s[t] = cnt;
    __syncthreads();
    #pragma unroll
    for (int d = SCAN_BLK / 2; d > 0; d >>= 1) {
        if (t < d) s[t] += s[t + d];
        __syncthreads();
    }
    if (t == 0) g_bsum[blockIdx.x] = s[0];
}

// 3b) one small block: exclusive scan of block sums.
__global__ void k_scan_tops(int nblocks) {
    __shared__ int s[MAX_SCAN_BLOCKS];
    int t = threadIdx.x;
    s[t] = (t < nblocks) ? g_bsum[t] : 0;
    __syncthreads();
    #pragma unroll
    for (int d = 1; d < MAX_SCAN_BLOCKS; d <<= 1) {
        int v = (t >= d) ? s[t - d] : 0;
        __syncthreads();
        s[t] += v;
        __syncthreads();
    }
    if (t < nblocks) g_btop[t] = s[t] - g_bsum[t];   // exclusive
}

// 3c) block-wide exclusive scan + block offset -> offsets & cursor.
__global__ void k_scan_final(int n, int E) {
    __shared__ int s[SCAN_BLK];
    int t = threadIdx.x;
    int i = blockIdx.x * SCAN_BLK + t;
    int cnt = (i < n) ? (int)(g_pack[i] >> CNT_SHIFT) : 0;
    s[t] = cnt;
    __syncthreads();
    #pragma unroll
    for (int d = 1; d < SCAN_BLK; d <<= 1) {
        int v = (t >= d) ? s[t - d] : 0;
        __syncthreads();
        s[t] += v;
        __syncthreads();
    }
    if (i < n) {
        int off = g_btop[blockIdx.x] + s[t] - cnt;   // exclusive
        g_offsets[i] = off;
        g_cursor[i]  = off;
    }
    if (i == 0) g_offsets[n] = E;
}

// 4) fill CSR: per edge, compute coef and scatter packed record under col bucket
__global__ void k_fill(const void* __restrict__ ei,
                       const float* __restrict__ ew, int E) {
    int e = blockIdx.x * blockDim.x + threadIdx.x;
    if (e < E) {
        int is64 = g_is64;
        int r = get_idx(ei, is64, e);
        int c = get_idx(ei, is64, (long)E + e);
        float coef = g_dinv[r] * ew[e] * g_dinv[c];
        int pos = atomicAdd(&g_cursor[c], 1);
        unsigned long long rec =
            (unsigned long long)(unsigned int)r |
            ((unsigned long long)__float_as_uint(coef) << 32);
        g_perm[pos] = rec;
    }
}

// 5) gather: one warp per node, lane l owns float4 chunk l.
//    out[c] = dinv[c]^2 * x[c] + sum_{e in CSR[c]} coef_e * x[row_e]
__global__ void k_gather(const float4* __restrict__ x,
                         float4* __restrict__ out, int n) {
    int w    = (blockIdx.x * blockDim.x + threadIdx.x) >> 5;
    int lane = threadIdx.x & 31;
    if (w >= n) return;

    float di = g_dinv[w];
    float s  = di * di;
    float4 v = __ldg(&x[(long)w * 32 + lane]);
    float4 acc;
    acc.x = v.x * s; acc.y = v.y * s; acc.z = v.z * s; acc.w = v.w * s;

    int beg = g_offsets[w];
    int end = g_offsets[w + 1];

    if (beg < end) {
        unsigned long long rec = g_perm[beg];   // software pipeline: prefetch rec
        for (int j = beg; j < end; j++) {
            unsigned long long next = (j + 1 < end) ? g_perm[j + 1] : 0ull;
            int   r  = (int)(unsigned int)(rec & 0xFFFFFFFFull);
            float cw = __uint_as_float((unsigned int)(rec >> 32));
            float4 xv = __ldg(&x[(long)r * 32 + lane]);
            acc.x += cw * xv.x;
            acc.y += cw * xv.y;
            acc.z += cw * xv.z;
            acc.w += cw * xv.w;
            rec = next;
        }
    }
    out[(long)w * 32 + lane] = acc;
}

// ---------------------------------------------------------------------------
extern "C" void kernel_launch(void* const* d_in, const int* in_sizes, int n_in,
                              void* d_out, int out_size) {
    // Bind inputs BY ELEMENT COUNT (robust to metadata ordering):
    //   x: N*128 f32 ; edge_weight: E f32 ; edge_index: 2E (i64 or i32, device-detected)
    int n = out_size / 128;

    const float* x = nullptr;
    int xi = -1;
    for (int i = 0; i < n_in; i++) {
        if (in_sizes[i] == n * 128) { x = (const float*)d_in[i]; xi = i; break; }
    }
    int ia = -1, ib = -1;
    for (int i = 0; i < n_in; i++) {
        if (i == xi) continue;
        if (ia < 0) ia = i; else ib = i;
    }
    const void* ei;
    const float* ew;
    int E;
    if (in_sizes[ia] > in_sizes[ib]) {
        ei = d_in[ia]; ew = (const float*)d_in[ib]; E = in_sizes[ib];
    } else {
        ei = d_in[ib]; ew = (const float*)d_in[ia]; E = in_sizes[ia];
    }

    float* out = (float*)d_out;

    int nscan = (n + SCAN_BLK - 1) / SCAN_BLK;    // <= 98 for N=100K

    k_setup       <<<(n + 255) / 256, 256>>>((const unsigned int*)ei, n);
    k_count_deg   <<<(E + 255) / 256, 256>>>(ei, ew, E);
    k_scan_partial<<<nscan, SCAN_BLK>>>(n);
    k_scan_tops   <<<1, MAX_SCAN_BLOCKS>>>(nscan);
    k_scan_final  <<<nscan, SCAN_BLK>>>(n, E);
    k_fill        <<<(E + 255) / 256, 256>>>(ei, ew, E);

    long long gt = (long long)n * 32;
    k_gather      <<<(int)((gt + 255) / 256), 256>>>((const float4*)x, (float4*)out, n);
}

// round 9
// speedup vs baseline: 2.5166x; 1.1249x over previous
#include <cuda_runtime.h>
#include <cstdint>

#define N_MAX 100000
#define E_MAX 3200000

// Fixed-point packing for fused (count | deg-sum) atomic:
//   bits [0:42)  : sum of ew in 20-bit fixed point (ew in [0,1))
//   bits [42:64) : edge count
#define FP_SCALE 1048576.0f          // 2^20
#define FP_INV   (1.0f / 1048576.0f)
#define CNT_SHIFT 42
#define SUM_MASK ((1ull << CNT_SHIFT) - 1ull)

#define SCAN_BLK 1024                 // elements (and threads) per scan block
#define MAX_SCAN_BLOCKS 128           // ceil(N_MAX/SCAN_BLK) = 98

// Scratch: __device__ globals (no allocation allowed)
__device__ unsigned long long g_pack[N_MAX];   // packed count|degsum
__device__ float g_dinv[N_MAX];
__device__ int   g_offsets[N_MAX + 1];
__device__ int   g_cursor[N_MAX];
__device__ int   g_bsum[MAX_SCAN_BLOCKS];      // per-block partial sums
__device__ int   g_btop[MAX_SCAN_BLOCKS];      // exclusive scan of g_bsum
__device__ unsigned long long g_perm[E_MAX];   // packed (row:int32 | ew:f32)
__device__ int   g_is64;                       // 1 if edge_index is int64, else int32

__device__ __forceinline__ int get_idx(const void* ei, int is64, long pos) {
    if (is64) return (int)((const long long*)ei)[pos];
    return ((const int*)ei)[pos];
}

// ---------------------------------------------------------------------------
// 1) setup: pack = 0; thread 0 detects index dtype (int64 has zero odd words).
__global__ void k_setup(const unsigned int* __restrict__ eiw, int n) {
    int i = blockIdx.x * blockDim.x + threadIdx.x;
    if (i < n) g_pack[i] = 0ull;
    if (i == 0) {
        int all0 = 1;
        #pragma unroll
        for (int k = 0; k < 64; k++) all0 &= (eiw[2 * k + 1] == 0u);
        g_is64 = all0;
    }
}

// 2) per edge: ONE packed atomic accumulates both count and deg-sum at col.
__global__ void k_count_deg(const void* __restrict__ ei,
                            const float* __restrict__ ew, int E) {
    int e = blockIdx.x * blockDim.x + threadIdx.x;
    if (e < E) {
        int is64 = g_is64;
        int c = get_idx(ei, is64, (long)E + e);
        unsigned long long inc =
            (1ull << CNT_SHIFT) |
            (unsigned long long)(ew[e] * FP_SCALE + 0.5f);
        atomicAdd(&g_pack[c], inc);
    }
}

// 3a) per-block partial sums of counts (coalesced) + fused dinv computation.
__global__ void k_scan_partial(int n) {
    __shared__ int s[SCAN_BLK];
    int t = threadIdx.x;
    int i = blockIdx.x * SCAN_BLK + t;
    int cnt = 0;
    if (i < n) {
        unsigned long long p = g_pack[i];
        cnt = (int)(p >> CNT_SHIFT);
        float deg = 1.0f + (float)(p & SUM_MASK) * FP_INV;
        g_dinv[i] = rsqrtf(deg);
    }
    s[t] = cnt;
    __syncthreads();
    #pragma unroll
    for (int d = SCAN_BLK / 2; d > 0; d >>= 1) {
        if (t < d) s[t] += s[t + d];
        __syncthreads();
    }
    if (t == 0) g_bsum[blockIdx.x] = s[0];
}

// 3b) one small block: exclusive scan of block sums.
__global__ void k_scan_tops(int nblocks) {
    __shared__ int s[MAX_SCAN_BLOCKS];
    int t = threadIdx.x;
    s[t] = (t < nblocks) ? g_bsum[t] : 0;
    __syncthreads();
    #pragma unroll
    for (int d = 1; d < MAX_SCAN_BLOCKS; d <<= 1) {
        int v = (t >= d) ? s[t - d] : 0;
        __syncthreads();
        s[t] += v;
        __syncthreads();
    }
    if (t < nblocks) g_btop[t] = s[t] - g_bsum[t];   // exclusive
}

// 3c) block-wide exclusive scan + block offset -> offsets & cursor.
__global__ void k_scan_final(int n, int E) {
    __shared__ int s[SCAN_BLK];
    int t = threadIdx.x;
    int i = blockIdx.x * SCAN_BLK + t;
    int cnt = (i < n) ? (int)(g_pack[i] >> CNT_SHIFT) : 0;
    s[t] = cnt;
    __syncthreads();
    #pragma unroll
    for (int d = 1; d < SCAN_BLK; d <<= 1) {
        int v = (t >= d) ? s[t - d] : 0;
        __syncthreads();
        s[t] += v;
        __syncthreads();
    }
    if (i < n) {
        int off = g_btop[blockIdx.x] + s[t] - cnt;   // exclusive
        g_offsets[i] = off;
        g_cursor[i]  = off;
    }
    if (i == 0) g_offsets[n] = E;
}

// 4) fill CSR: per edge, store raw (row, ew) record under col bucket.
//    NO dinv reads here -- dinv[r] applied in gather (broadcast load),
//    dinv[c] factored out of the whole sum.
__global__ void k_fill(const void* __restrict__ ei,
                       const float* __restrict__ ew, int E) {
    int e = blockIdx.x * blockDim.x + threadIdx.x;
    if (e < E) {
        int is64 = g_is64;
        int r = get_idx(ei, is64, e);
        int c = get_idx(ei, is64, (long)E + e);
        int pos = atomicAdd(&g_cursor[c], 1);
        unsigned long long rec =
            (unsigned long long)(unsigned int)r |
            ((unsigned long long)__float_as_uint(ew[e]) << 32);
        g_perm[pos] = rec;
    }
}

// 5) gather: one warp per node, lane l owns float4 chunk l.
//    out[c] = dinv[c] * ( dinv[c]*x[c] + sum_e dinv[r_e]*ew_e*x[r_e] )
__global__ void k_gather(const float4* __restrict__ x,
                         float4* __restrict__ out, int n) {
    int w    = (blockIdx.x * blockDim.x + threadIdx.x) >> 5;
    int lane = threadIdx.x & 31;
    if (w >= n) return;

    float dc = g_dinv[w];
    float4 v = __ldg(&x[(long)w * 32 + lane]);
    float4 acc;
    acc.x = v.x * dc; acc.y = v.y * dc; acc.z = v.z * dc; acc.w = v.w * dc;

    int beg = g_offsets[w];
    int end = g_offsets[w + 1];

    if (beg < end) {
        unsigned long long rec = g_perm[beg];   // software pipeline: prefetch rec
        for (int j = beg; j < end; j++) {
            unsigned long long next = (j + 1 < end) ? g_perm[j + 1] : 0ull;
            int   r  = (int)(unsigned int)(rec & 0xFFFFFFFFull);
            float we = __uint_as_float((unsigned int)(rec >> 32));
            // dinv[r] broadcast load runs parallel to the x-row gather
            float cw = g_dinv[r] * we;
            float4 xv = __ldg(&x[(long)r * 32 + lane]);
            acc.x += cw * xv.x;
            acc.y += cw * xv.y;
            acc.z += cw * xv.z;
            acc.w += cw * xv.w;
            rec = next;
        }
    }
    float4 o;
    o.x = acc.x * dc; o.y = acc.y * dc; o.z = acc.z * dc; o.w = acc.w * dc;
    out[(long)w * 32 + lane] = o;
}

// ---------------------------------------------------------------------------
extern "C" void kernel_launch(void* const* d_in, const int* in_sizes, int n_in,
                              void* d_out, int out_size) {
    // Bind inputs BY ELEMENT COUNT (robust to metadata ordering):
    //   x: N*128 f32 ; edge_weight: E f32 ; edge_index: 2E (i64 or i32, device-detected)
    int n = out_size / 128;

    const float* x = nullptr;
    int xi = -1;
    for (int i = 0; i < n_in; i++) {
        if (in_sizes[i] == n * 128) { x = (const float*)d_in[i]; xi = i; break; }
    }
    int ia = -1, ib = -1;
    for (int i = 0; i < n_in; i++) {
        if (i == xi) continue;
        if (ia < 0) ia = i; else ib = i;
    }
    const void* ei;
    const float* ew;
    int E;
    if (in_sizes[ia] > in_sizes[ib]) {
        ei = d_in[ia]; ew = (const float*)d_in[ib]; E = in_sizes[ib];
    } else {
        ei = d_in[ib]; ew = (const float*)d_in[ia]; E = in_sizes[ia];
    }

    float* out = (float*)d_out;

    int nscan = (n + SCAN_BLK - 1) / SCAN_BLK;    // <= 98 for N=100K

    k_setup       <<<(n + 255) / 256, 256>>>((const unsigned int*)ei, n);
    k_count_deg   <<<(E + 255) / 256, 256>>>(ei, ew, E);
    k_scan_partial<<<nscan, SCAN_BLK>>>(n);
    k_scan_tops   <<<1, MAX_SCAN_BLOCKS>>>(nscan);
    k_scan_final  <<<nscan, SCAN_BLK>>>(n, E);
    k_fill        <<<(E + 255) / 256, 256>>>(ei, ew, E);

    long long gt = (long long)n * 32;
    k_gather      <<<(int)((gt + 255) / 256), 256>>>((const float4*)x, (float4*)out, n);
}